// round 3
// baseline (speedup 1.0000x reference)
#include <cuda_runtime.h>
#include <stdint.h>

// Problem constants (fixed by setup_inputs)
#define B_  16
#define C_  64
#define IH_ 256
#define IW_ 256
#define OH_ 256
#define OW_ 256
#define CH_STRIDE (IH_*IW_)          // 65536
#define IMG_STRIDE (C_*CH_STRIDE)    // per-batch input stride
#define OUT_ELEMS ((long long)B_*C_*OH_*OW_)

__global__ __launch_bounds__(256)
void affine_sample_kernel(const float* __restrict__ inp,
                          const float* __restrict__ theta,
                          float* __restrict__ out)
{
    // block = one (b, oh) row; thread = ow
    const int bo = blockIdx.x;
    const int b  = bo >> 8;          // bo / OH_
    const int oh = bo & 255;         // bo % OH_
    const int ow = threadIdx.x;

    // theta row for this batch (broadcast via L1/const path)
    const float* tb = theta + b * 6;
    const float t00 = __ldg(tb + 0), t01 = __ldg(tb + 1), t02 = __ldg(tb + 2);
    const float t10 = __ldg(tb + 3), t11 = __ldg(tb + 4), t12 = __ldg(tb + 5);

    // linspace(-1,1,N): -1 + i * 2/(N-1)
    const float ww = fmaf((float)ow, 2.0f / 255.0f, -1.0f);
    const float hh = fmaf((float)oh, 2.0f / 255.0f, -1.0f);

    const float gx = fmaf(t00, ww, fmaf(t01, hh, t02));
    const float gy = fmaf(t10, ww, fmaf(t11, hh, t12));

    // align_corners=True mapping
    const float ix = (gx + 1.0f) * 0.5f * (float)(IW_ - 1);
    const float iy = (gy + 1.0f) * 0.5f * (float)(IH_ - 1);

    const float x0f = floorf(ix);
    const float y0f = floorf(iy);
    const float x1f = x0f + 1.0f;
    const float y1f = y0f + 1.0f;

    const float wx1 = ix - x0f;
    const float wy1 = iy - y0f;
    const float wx0 = 1.0f - wx1;
    const float wy0 = 1.0f - wy1;

    const bool inx0 = (x0f >= 0.0f) & (x0f <= (float)(IW_ - 1));
    const bool inx1 = (x1f >= 0.0f) & (x1f <= (float)(IW_ - 1));
    const bool iny0 = (y0f >= 0.0f) & (y0f <= (float)(IH_ - 1));
    const bool iny1 = (y1f >= 0.0f) & (y1f <= (float)(IH_ - 1));

    float w00 = (inx0 & iny0) ? wx0 * wy0 : 0.0f;
    float w10 = (inx1 & iny0) ? wx1 * wy0 : 0.0f;
    float w01 = (inx0 & iny1) ? wx0 * wy1 : 0.0f;
    float w11 = (inx1 & iny1) ? wx1 * wy1 : 0.0f;

    // clamped integer indices (only used where weight != 0)
    const int x0i = min(max((int)x0f, 0), IW_ - 1);
    const int x1i = min(max((int)x1f, 0), IW_ - 1);
    const int y0i = min(max((int)y0f, 0), IH_ - 1);
    const int y1i = min(max((int)y1f, 0), IH_ - 1);

    const int o00 = y0i * IW_ + x0i;
    const int o10 = y0i * IW_ + x1i;
    const int o01 = y1i * IW_ + x0i;
    const int o11 = y1i * IW_ + x1i;

    float* op = out + ((long long)b * C_ * OH_ + oh) * OW_ + ow;

    const bool any = (w00 != 0.0f) | (w10 != 0.0f) | (w01 != 0.0f) | (w11 != 0.0f);

    if (!any) {
        // fully out-of-bounds pixel: pure zero stream (no reads)
        #pragma unroll 8
        for (int c = 0; c < C_; ++c) {
            op[(long long)c * (OH_ * OW_)] = 0.0f;
        }
        return;
    }

    const float* base = inp + (long long)b * IMG_STRIDE;
    const bool l00 = (w00 != 0.0f);
    const bool l10 = (w10 != 0.0f);
    const bool l01 = (w01 != 0.0f);
    const bool l11 = (w11 != 0.0f);

    #pragma unroll 4
    for (int c = 0; c < C_; ++c) {
        const float* ch = base + (long long)c * CH_STRIDE;
        float v00 = l00 ? __ldg(ch + o00) : 0.0f;
        float v10 = l10 ? __ldg(ch + o10) : 0.0f;
        float v01 = l01 ? __ldg(ch + o01) : 0.0f;
        float v11 = l11 ? __ldg(ch + o11) : 0.0f;
        float acc = v00 * w00;
        acc = fmaf(v10, w10, acc);
        acc = fmaf(v01, w01, acc);
        acc = fmaf(v11, w11, acc);
        op[(long long)c * (OH_ * OW_)] = acc;
    }
}

__global__ void vertices_kernel(const float* __restrict__ theta,
                                float* __restrict__ vert)
{
    // 16 batches * 4 vertices
    const int idx = threadIdx.x;
    if (idx >= B_ * 4) return;
    const int b = idx >> 2;
    const int v = idx & 3;

    // VERTICES = [(-1,-1,1), (-1,1,1), (1,1,1), (1,-1,1)]
    const float vx = (v >= 2) ? 1.0f : -1.0f;
    const float vy = (v == 1 || v == 2) ? 1.0f : -1.0f;

    const float* tb = theta + b * 6;
    const float ox = tb[0] * vx + tb[1] * vy + tb[2];
    const float oy = tb[3] * vx + tb[4] * vy + tb[5];

    vert[idx * 2 + 0] = (ox + 1.0f) * ((float)IW_ * 0.5f);
    vert[idx * 2 + 1] = (oy + 1.0f) * ((float)IH_ * 0.5f);
}

extern "C" void kernel_launch(void* const* d_in, const int* in_sizes, int n_in,
                              void* d_out, int out_size)
{
    const float* inp   = (const float*)d_in[0];
    const float* theta = (const float*)d_in[1];
    float* out = (float*)d_out;

    // Tuple output flattening: [B,C,OH,OW] image first, then [B,4,2] vertices.
    float* vert = out + (out_size - B_ * 4 * 2);

    affine_sample_kernel<<<B_ * OH_, OW_>>>(inp, theta, out);
    vertices_kernel<<<1, 128>>>(theta, vert);
}

// round 4
// speedup vs baseline: 1.1890x; 1.1890x over previous
#include <cuda_runtime.h>

// Problem constants (fixed by setup_inputs)
#define B_  16
#define C_  64
#define IH_ 256
#define IW_ 256
#define CH_STRIDE (IH_*IW_)          // 65536
#define IMG_STRIDE (C_*CH_STRIDE)    // per-batch input stride

// Block = one 32x32 output tile of one batch. 256 threads, 4 pixels each.
// Lane axis (ow vs oh) chosen per batch to minimize per-instruction sector
// scatter of the bilinear gathers. Mode B (lanes along oh) stages stores
// through a padded smem tile to keep global writes coalesced.
__global__ __launch_bounds__(256)
void affine_fused_kernel(const float* __restrict__ inp,
                         const float* __restrict__ theta,
                         float* __restrict__ out,
                         float* __restrict__ vert)
{
    __shared__ float sm[4][32][33];   // [chan-sub][oh][ow+pad] 16.9 KB

    const int blk  = blockIdx.x;
    const int b    = blk >> 6;              // 64 tiles per batch (8x8)
    const int tile = blk & 63;
    const int oh0  = (tile >> 3) << 5;
    const int ow0  = (tile & 7) << 5;
    const int tid  = threadIdx.x;
    const int lane = tid & 31;
    const int wrp  = tid >> 5;

    // ---- vertices (fused; block 0 only, independent of main work) ----
    if (blk == 0 && tid < B_ * 4) {
        const int vb = tid >> 2;
        const int v  = tid & 3;
        // VERTICES = [(-1,-1), (-1,1), (1,1), (1,-1)] (z=1)
        const float vx = (v >= 2) ? 1.0f : -1.0f;
        const float vy = (v == 1 || v == 2) ? 1.0f : -1.0f;
        const float* tv = theta + vb * 6;
        const float ox = tv[0] * vx + tv[1] * vy + tv[2];
        const float oy = tv[3] * vx + tv[4] * vy + tv[5];
        vert[tid * 2 + 0] = (ox + 1.0f) * ((float)IW_ * 0.5f);
        vert[tid * 2 + 1] = (oy + 1.0f) * ((float)IH_ * 0.5f);
    }

    const float* tb = theta + b * 6;
    const float t00 = tb[0], t01 = tb[1], t02 = tb[2];
    const float t10 = tb[3], t11 = tb[4], t12 = tb[5];

    // Per-lane input-space step when lanes run along ow: (t00, t10);
    // along oh: (t01, t11). Sector scatter ~ |dy| + |dx|/8.
    const float mA = fabsf(t10) + 0.125f * fabsf(t00);   // lanes along ow
    const float mB = fabsf(t11) + 0.125f * fabsf(t01);   // lanes along oh
    const bool modeB = (mB < mA);

    int   offs[4][4];
    float wgt [4][4];
    bool  any [4];
    int   ohl [4], owl[4];

    #pragma unroll
    for (int k = 0; k < 4; ++k) {
        const int oh_l = modeB ? lane : (wrp + 8 * k);
        const int ow_l = modeB ? (wrp + 8 * k) : lane;
        ohl[k] = oh_l; owl[k] = ow_l;

        const float wwv = fmaf((float)(ow0 + ow_l), 2.0f / 255.0f, -1.0f);
        const float hhv = fmaf((float)(oh0 + oh_l), 2.0f / 255.0f, -1.0f);

        const float gx = fmaf(t00, wwv, fmaf(t01, hhv, t02));
        const float gy = fmaf(t10, wwv, fmaf(t11, hhv, t12));

        const float ix = (gx + 1.0f) * 0.5f * 255.0f;   // align_corners=True
        const float iy = (gy + 1.0f) * 0.5f * 255.0f;

        const float x0f = floorf(ix);
        const float y0f = floorf(iy);
        const float wx1 = ix - x0f;
        const float wy1 = iy - y0f;
        const float wx0 = 1.0f - wx1;
        const float wy0 = 1.0f - wy1;

        const bool inx0 = (x0f >=  0.0f) && (x0f <= 255.0f);
        const bool inx1 = (x0f >= -1.0f) && (x0f <= 254.0f);
        const bool iny0 = (y0f >=  0.0f) && (y0f <= 255.0f);
        const bool iny1 = (y0f >= -1.0f) && (y0f <= 254.0f);

        const float w00 = (inx0 && iny0) ? wx0 * wy0 : 0.0f;
        const float w10 = (inx1 && iny0) ? wx1 * wy0 : 0.0f;
        const float w01 = (inx0 && iny1) ? wx0 * wy1 : 0.0f;
        const float w11 = (inx1 && iny1) ? wx1 * wy1 : 0.0f;

        const int x0i = min(max((int)x0f,     0), IW_ - 1);
        const int x1i = min(max((int)x0f + 1, 0), IW_ - 1);
        const int y0i = min(max((int)y0f,     0), IH_ - 1);
        const int y1i = min(max((int)y0f + 1, 0), IH_ - 1);

        offs[k][0] = y0i * IW_ + x0i;
        offs[k][1] = y0i * IW_ + x1i;
        offs[k][2] = y1i * IW_ + x0i;
        offs[k][3] = y1i * IW_ + x1i;
        wgt[k][0] = w00; wgt[k][1] = w10; wgt[k][2] = w01; wgt[k][3] = w11;
        any[k] = (w00 + w10 + w01 + w11) != 0.0f;
    }

    const float* base = inp + (long long)b * IMG_STRIDE;
    const long long out_b = (long long)b * C_ * IH_ * IW_;

    for (int c0 = 0; c0 < C_; c0 += 4) {
        #pragma unroll
        for (int cc = 0; cc < 4; ++cc) {
            const float* ch = base + (long long)(c0 + cc) * CH_STRIDE;
            #pragma unroll
            for (int k = 0; k < 4; ++k) {
                float acc = 0.0f;
                if (any[k]) {
                    acc =      wgt[k][0] * __ldg(ch + offs[k][0]);
                    acc = fmaf(wgt[k][1], __ldg(ch + offs[k][1]), acc);
                    acc = fmaf(wgt[k][2], __ldg(ch + offs[k][2]), acc);
                    acc = fmaf(wgt[k][3], __ldg(ch + offs[k][3]), acc);
                }
                if (!modeB) {
                    out[out_b + ((long long)(c0 + cc) * IH_ + (oh0 + ohl[k])) * IW_
                              + ow0 + owl[k]] = acc;
                } else {
                    sm[cc][ohl[k]][owl[k]] = acc;
                }
            }
        }
        if (modeB) {
            __syncthreads();
            #pragma unroll
            for (int cc = 0; cc < 4; ++cc) {
                #pragma unroll
                for (int k = 0; k < 4; ++k) {
                    const int r = wrp + 8 * k;
                    const float v = sm[cc][r][lane];
                    out[out_b + ((long long)(c0 + cc) * IH_ + (oh0 + r)) * IW_
                              + ow0 + lane] = v;
                }
            }
            __syncthreads();
        }
    }
}

extern "C" void kernel_launch(void* const* d_in, const int* in_sizes, int n_in,
                              void* d_out, int out_size)
{
    const float* inp   = (const float*)d_in[0];
    const float* theta = (const float*)d_in[1];
    float* out = (float*)d_out;

    // Tuple output flattening: [B,C,OH,OW] image first, then [B,4,2] vertices.
    float* vert = out + (out_size - B_ * 4 * 2);

    affine_fused_kernel<<<B_ * 64, 256>>>(inp, theta, out, vert);
}

// round 5
// speedup vs baseline: 1.4053x; 1.1819x over previous
#include <cuda_runtime.h>

// Problem constants (fixed by setup_inputs)
#define B_  16
#define C_  64
#define IH_ 256
#define IW_ 256
#define CH_STRIDE (IH_*IW_)          // 65536
#define IMG_STRIDE (C_*CH_STRIDE)

// Block = 32(ow) x 16(oh) output tile of one batch. 256 threads, 2 px/thread.
// Per-batch warp-lane geometry:
//   mode A: lanes along ow (32x1)  -> perfect stores, rows ~ 32|t10|
//   mode P: 8x4 lane patch         -> rows ~ 8|t10|+4|t11| (bounded scatter),
//                                     stores = 4x 32B lines per warp.
__global__ __launch_bounds__(256)
void affine_fused_kernel(const float* __restrict__ inp,
                         const float* __restrict__ theta,
                         float* __restrict__ out,
                         float* __restrict__ vert)
{
    const int blk  = blockIdx.x;
    const int b    = blk >> 7;               // 128 tiles per batch (8 x 16)
    const int tile = blk & 127;
    const int ow0  = (tile & 7)  << 5;       // 8 tiles across ow
    const int oh0  = (tile >> 3) << 4;       // 16 tiles down oh
    const int tid  = threadIdx.x;
    const int lane = tid & 31;
    const int wrp  = tid >> 5;

    // ---- vertices (fused; block 0 only) ----
    if (blk == 0 && tid < B_ * 4) {
        const int vb = tid >> 2;
        const int v  = tid & 3;
        const float vx = (v >= 2) ? 1.0f : -1.0f;          // [-1,-1,1,1]
        const float vy = (v == 1 || v == 2) ? 1.0f : -1.0f; // [-1,1,1,-1]
        const float* tv = theta + vb * 6;
        const float ox = tv[0] * vx + tv[1] * vy + tv[2];
        const float oy = tv[3] * vx + tv[4] * vy + tv[5];
        vert[tid * 2 + 0] = (ox + 1.0f) * ((float)IW_ * 0.5f);
        vert[tid * 2 + 1] = (oy + 1.0f) * ((float)IH_ * 0.5f);
    }

    const float* tb = theta + b * 6;
    const float t00 = tb[0], t01 = tb[1], t02 = tb[2];
    const float t10 = tb[3], t11 = tb[4], t12 = tb[5];

    // Input-space step per output pixel is exactly (t00,t10) along ow and
    // (t01,t11) along oh. Estimate L1 sector cost per gather + store lines.
    const float costA = 32.0f * fabsf(t10) + 4.0f * fabsf(t00) + 2.0f;
    const float costP = 8.0f * fabsf(t10) + 4.0f * fabsf(t11)
                      + fabsf(t00) + 0.5f * fabsf(t01) + 5.0f;
    const bool modeP = (costP < costA);

    int   offs[2][4];
    float wgt [2][4];
    bool  any [2];
    int   ohl [2], owl[2];

    #pragma unroll
    for (int k = 0; k < 2; ++k) {
        int oh_l, ow_l;
        if (modeP) {
            // 16 patches of 8x4: col = wrp&3, patch-row = (wrp>>2)*2 + k
            const int prow = ((wrp >> 2) << 1) + k;
            oh_l = (prow << 2) + (lane >> 3);
            ow_l = ((wrp & 3) << 3) + (lane & 7);
        } else {
            oh_l = wrp + 8 * k;
            ow_l = lane;
        }
        ohl[k] = oh_l; owl[k] = ow_l;

        const float wwv = fmaf((float)(ow0 + ow_l), 2.0f / 255.0f, -1.0f);
        const float hhv = fmaf((float)(oh0 + oh_l), 2.0f / 255.0f, -1.0f);

        const float gx = fmaf(t00, wwv, fmaf(t01, hhv, t02));
        const float gy = fmaf(t10, wwv, fmaf(t11, hhv, t12));

        const float ix = (gx + 1.0f) * 0.5f * 255.0f;   // align_corners=True
        const float iy = (gy + 1.0f) * 0.5f * 255.0f;

        const float x0f = floorf(ix);
        const float y0f = floorf(iy);
        const float wx1 = ix - x0f;
        const float wy1 = iy - y0f;
        const float wx0 = 1.0f - wx1;
        const float wy0 = 1.0f - wy1;

        const bool inx0 = (x0f >=  0.0f) && (x0f <= 255.0f);
        const bool inx1 = (x0f >= -1.0f) && (x0f <= 254.0f);
        const bool iny0 = (y0f >=  0.0f) && (y0f <= 255.0f);
        const bool iny1 = (y0f >= -1.0f) && (y0f <= 254.0f);

        wgt[k][0] = (inx0 && iny0) ? wx0 * wy0 : 0.0f;
        wgt[k][1] = (inx1 && iny0) ? wx1 * wy0 : 0.0f;
        wgt[k][2] = (inx0 && iny1) ? wx0 * wy1 : 0.0f;
        wgt[k][3] = (inx1 && iny1) ? wx1 * wy1 : 0.0f;

        const int x0i = min(max((int)x0f,     0), IW_ - 1);
        const int x1i = min(max((int)x0f + 1, 0), IW_ - 1);
        const int y0i = min(max((int)y0f,     0), IH_ - 1);
        const int y1i = min(max((int)y0f + 1, 0), IH_ - 1);

        offs[k][0] = y0i * IW_ + x0i;
        offs[k][1] = y0i * IW_ + x1i;
        offs[k][2] = y1i * IW_ + x0i;
        offs[k][3] = y1i * IW_ + x1i;
        any[k] = (wgt[k][0] + wgt[k][1] + wgt[k][2] + wgt[k][3]) != 0.0f;
    }

    const float* base = inp + (long long)b * IMG_STRIDE;
    float* ob0 = out + (long long)b * C_ * CH_STRIDE
                     + (oh0 + ohl[0]) * IW_ + ow0 + owl[0];
    float* ob1 = out + (long long)b * C_ * CH_STRIDE
                     + (oh0 + ohl[1]) * IW_ + ow0 + owl[1];

    #pragma unroll 1
    for (int c0 = 0; c0 < C_; c0 += 2) {
        #pragma unroll
        for (int cc = 0; cc < 2; ++cc) {
            const float* ch = base + (long long)(c0 + cc) * CH_STRIDE;
            float a0 = 0.0f, a1 = 0.0f;
            if (any[0]) {
                a0 =      wgt[0][0] * __ldg(ch + offs[0][0]);
                a0 = fmaf(wgt[0][1], __ldg(ch + offs[0][1]), a0);
                a0 = fmaf(wgt[0][2], __ldg(ch + offs[0][2]), a0);
                a0 = fmaf(wgt[0][3], __ldg(ch + offs[0][3]), a0);
            }
            if (any[1]) {
                a1 =      wgt[1][0] * __ldg(ch + offs[1][0]);
                a1 = fmaf(wgt[1][1], __ldg(ch + offs[1][1]), a1);
                a1 = fmaf(wgt[1][2], __ldg(ch + offs[1][2]), a1);
                a1 = fmaf(wgt[1][3], __ldg(ch + offs[1][3]), a1);
            }
            ob0[(long long)(c0 + cc) * CH_STRIDE] = a0;
            ob1[(long long)(c0 + cc) * CH_STRIDE] = a1;
        }
    }
}

extern "C" void kernel_launch(void* const* d_in, const int* in_sizes, int n_in,
                              void* d_out, int out_size)
{
    const float* inp   = (const float*)d_in[0];
    const float* theta = (const float*)d_in[1];
    float* out = (float*)d_out;

    // Tuple output flattening: [B,C,OH,OW] image first, then [B,4,2] vertices.
    float* vert = out + (out_size - B_ * 4 * 2);

    affine_fused_kernel<<<B_ * 128, 256>>>(inp, theta, out, vert);
}